// round 4
// baseline (speedup 1.0000x reference)
#include <cuda_runtime.h>
#include <float.h>

#define NB   8192
#define NBAT 16
#define MS   1024
#define KNN  16
#define PPT  8        // points per thread in FPS (8192 / 1024)
#define CH   2048     // KNN shared-memory chunk (points)

// ---------------------------------------------------------------------------
// Kernel 1: farthest point sampling. One CTA per batch, 1024 threads.
// Points in registers (8/thread, strided); full pos copy in SMEM for O(LDS)
// centroid broadcast. Argmax via packed u64 key (float bits << 32 | ~idx):
// max key == max value, ties -> lowest index == jnp.argmax semantics.
// Arithmetic: d2 = ((dx*dx + dy*dy) + dz*dz), all rn, min via fminf —
// VERIFIED bitwise-identical to the reference (output 0 rel_err = 0).
// ---------------------------------------------------------------------------
__global__ __launch_bounds__(1024, 1)
void fps_kernel(const float* __restrict__ pos, float* __restrict__ out_cent) {
    extern __shared__ float sh[];
    float* shx = sh;
    float* shy = sh + NB;
    float* shz = sh + 2 * NB;
    unsigned long long* shred = (unsigned long long*)(sh + 3 * NB);  // 32 slots
    int* shcur = (int*)(shred + 32);

    const int b   = blockIdx.x;
    const int tid = threadIdx.x;
    const float* pb = pos + (size_t)b * NB * 3;

    for (int i = tid; i < NB; i += 1024) {
        shx[i] = pb[3 * i + 0];
        shy[i] = pb[3 * i + 1];
        shz[i] = pb[3 * i + 2];
    }
    __syncthreads();

    float rx[PPT], ry[PPT], rz[PPT], md[PPT];
#pragma unroll
    for (int k = 0; k < PPT; k++) {
        int i = tid + (k << 10);
        rx[k] = shx[i];
        ry[k] = shy[i];
        rz[k] = shz[i];
        md[k] = FLT_MAX;
    }

    int cur = 0;
    for (int s = 0;; s++) {
        float qx = shx[cur], qy = shy[cur], qz = shz[cur];
        if (tid == 0) {
            float* oc = out_cent + ((size_t)b * MS + s) * 3;
            oc[0] = qx; oc[1] = qy; oc[2] = qz;
        }
        if (s == MS - 1) break;

        // distance pass + running local argmax (ascending k -> ascending idx,
        // strict > keeps lowest index on ties)
        float bv = -1.0f;
        int   bk = 0;
#pragma unroll
        for (int k = 0; k < PPT; k++) {
            float dx = __fsub_rn(rx[k], qx);
            float dy = __fsub_rn(ry[k], qy);
            float dz = __fsub_rn(rz[k], qz);
            float d2 = __fadd_rn(__fadd_rn(__fmul_rn(dx, dx), __fmul_rn(dy, dy)),
                                 __fmul_rn(dz, dz));
            float m = fminf(md[k], d2);
            md[k] = m;
            if (m > bv) { bv = m; bk = k; }
        }

        unsigned ii = (unsigned)(tid + (bk << 10));
        unsigned long long key =
            ((unsigned long long)__float_as_uint(bv) << 32) |
            (unsigned long long)(0xFFFFFFFFu - ii);

#pragma unroll
        for (int o = 16; o; o >>= 1) {
            unsigned long long other = __shfl_down_sync(0xFFFFFFFFu, key, o);
            if (other > key) key = other;
        }
        const int lane = tid & 31, w = tid >> 5;
        if (lane == 0) shred[w] = key;
        __syncthreads();
        if (w == 0) {
            unsigned long long k2 = shred[lane];
#pragma unroll
            for (int o = 16; o; o >>= 1) {
                unsigned long long other = __shfl_down_sync(0xFFFFFFFFu, k2, o);
                if (other > k2) k2 = other;
            }
            if (lane == 0) shcur[0] = (int)(0xFFFFFFFFu - (unsigned)k2);
        }
        __syncthreads();
        cur = shcur[0];
    }
}

// ---------------------------------------------------------------------------
// Kernel 2: brute-force 16-NN + group gather. One thread per centroid.
// Batch points staged through SMEM as float4{x,y,z,|p|^2} (broadcast LDS).
// Sorted top-16 register list, branchless shift chain, d2 < dist[15] guard.
//
// d2 matches the reference pipeline op-for-op:
//   csum, psum : elementwise square -> rn add chain (XLA reduce lowering —
//                verified bitwise by output 0)
//   dot        : GEMM-style FMA accumulation over k ascending:
//                fma(cz,pz, fma(cy,py, cx*px))   <-- THE FIX (was mul/add/add)
//   d2         : ((csum - 2*dot) + psum), left-assoc, all rn.
// Strict '<' + ascending scan order reproduce lax.top_k stable tie-breaking.
// ---------------------------------------------------------------------------
__global__ __launch_bounds__(128, 4)
void knn_kernel(const float* __restrict__ pos, const float* __restrict__ cent,
                float* __restrict__ out_grp) {
    __shared__ float4 shp[CH];
    const int b = blockIdx.x >> 3;
    const int m = ((blockIdx.x & 7) << 7) + threadIdx.x;

    const float* cp = cent + ((size_t)b * MS + m) * 3;
    const float cx = cp[0], cy = cp[1], cz = cp[2];
    const float csum = __fadd_rn(__fadd_rn(__fmul_rn(cx, cx), __fmul_rn(cy, cy)),
                                 __fmul_rn(cz, cz));
    const float* pb = pos + (size_t)b * NB * 3;

    float dist[KNN];
    int   idx[KNN];
#pragma unroll
    for (int k = 0; k < KNN; k++) { dist[k] = FLT_MAX; idx[k] = 0; }

    for (int c0 = 0; c0 < NB; c0 += CH) {
        __syncthreads();
        for (int j = threadIdx.x; j < CH; j += 128) {
            float px = pb[3 * (c0 + j) + 0];
            float py = pb[3 * (c0 + j) + 1];
            float pz = pb[3 * (c0 + j) + 2];
            float ps = __fadd_rn(__fadd_rn(__fmul_rn(px, px), __fmul_rn(py, py)),
                                 __fmul_rn(pz, pz));
            shp[j] = make_float4(px, py, pz, ps);
        }
        __syncthreads();

        for (int j = 0; j < CH; j++) {
            float4 p = shp[j];
            // GEMM fma chain over the contraction dim (k = 0,1,2):
            float dot = __fmaf_rn(cz, p.z,
                        __fmaf_rn(cy, p.y,
                        __fmul_rn(cx, p.x)));
            float d2 = __fadd_rn(__fsub_rn(csum, __fmul_rn(2.0f, dot)), p.w);
            if (d2 < dist[KNN - 1]) {
                bool cpn = true;  // d2 < dist[15] (guard)
#pragma unroll
                for (int q = KNN - 1; q >= 1; q--) {
                    bool cq = d2 < dist[q - 1];
                    dist[q] = cq ? dist[q - 1] : (cpn ? d2 : dist[q]);
                    idx[q]  = cq ? idx[q - 1]  : (cpn ? (c0 + j) : idx[q]);
                    cpn = cq;
                }
                if (cpn) { dist[0] = d2; idx[0] = c0 + j; }
            }
        }
    }

    float* og = out_grp + (size_t)(b * MS + m) * KNN * 3;
#pragma unroll
    for (int k = 0; k < KNN; k++) {
        int i = idx[k];
        og[3 * k + 0] = pb[3 * i + 0];
        og[3 * k + 1] = pb[3 * i + 1];
        og[3 * k + 2] = pb[3 * i + 2];
    }
}

// ---------------------------------------------------------------------------
// kernel_launch: d_in = [x (unused), pos, batch]; out = [centroids | groups].
// Graph-capturable: two kernel launches, no allocs, no syncs.
// ---------------------------------------------------------------------------
extern "C" void kernel_launch(void* const* d_in, const int* in_sizes, int n_in,
                              void* d_out, int out_size) {
    (void)in_sizes; (void)n_in; (void)out_size;
    const float* pos = (const float*)d_in[1];
    float* out      = (float*)d_out;
    float* out_cent = out;                              // B*M*3   = 49152
    float* out_grp  = out + (size_t)NBAT * MS * 3;      // B*M*K*3 = 786432

    const size_t fps_smem = (size_t)3 * NB * sizeof(float) + 33 * 8 + 16;
    cudaFuncSetAttribute(fps_kernel, cudaFuncAttributeMaxDynamicSharedMemorySize,
                         (int)fps_smem);

    fps_kernel<<<NBAT, 1024, fps_smem>>>(pos, out_cent);
    knn_kernel<<<NBAT * 8, 128>>>(pos, out_cent, out_grp);
}

// round 5
// speedup vs baseline: 1.7843x; 1.7843x over previous
#include <cuda_runtime.h>
#include <float.h>

#define NB   8192
#define NBAT 16
#define MS   1024
#define KNN  16
#define PPT  8        // FPS points per thread (8192 / 1024)
#define CH   2048     // KNN shared-memory chunk (points)
#define KW   8        // KNN warps per CTA (centroids per CTA)

// ---- f32x2 helpers: two independent rn fp32 ops per instruction -----------
__device__ __forceinline__ unsigned long long f2pack(float lo, float hi) {
    unsigned long long d;
    asm("mov.b64 %0, {%1, %2};" : "=l"(d)
        : "r"(__float_as_uint(lo)), "r"(__float_as_uint(hi)));
    return d;
}
__device__ __forceinline__ void f2unpack(float& lo, float& hi, unsigned long long s) {
    unsigned a, b;
    asm("mov.b64 {%0, %1}, %2;" : "=r"(a), "=r"(b) : "l"(s));
    lo = __uint_as_float(a); hi = __uint_as_float(b);
}
__device__ __forceinline__ unsigned long long f2add(unsigned long long a,
                                                    unsigned long long b) {
    unsigned long long d;
    asm("add.rn.f32x2 %0, %1, %2;" : "=l"(d) : "l"(a), "l"(b));
    return d;
}
__device__ __forceinline__ unsigned long long f2mul(unsigned long long a,
                                                    unsigned long long b) {
    unsigned long long d;
    asm("mul.rn.f32x2 %0, %1, %2;" : "=l"(d) : "l"(a), "l"(b));
    return d;
}

// ---------------------------------------------------------------------------
// Kernel 1: farthest point sampling. One CTA per batch, 1024 threads.
// Distance pass uses packed f32x2 mul/add in the verified association
// ((dx*dx + dy*dy) + dz*dz) — bitwise identical per lane to the reference
// (no FMA contraction; subtract = add of exactly-negated q).
// Argmax: value-only fmax reduce (order-independent), then threads matching
// the global max recover their lowest local index and atomicMin into SMEM —
// exact jnp.argmax first-occurrence semantics.
// ---------------------------------------------------------------------------
__global__ __launch_bounds__(1024, 1)
void fps_kernel(const float* __restrict__ pos, float* __restrict__ out_cent) {
    extern __shared__ float sh[];
    float* shx = sh;
    float* shy = sh + NB;
    float* shz = sh + 2 * NB;
    __shared__ float shredf[32];
    __shared__ float shmax;
    __shared__ int   shidx;

    const int b    = blockIdx.x;
    const int tid  = threadIdx.x;
    const int lane = tid & 31;
    const int w    = tid >> 5;
    const float* pb = pos + (size_t)b * NB * 3;

    for (int i = tid; i < NB; i += 1024) {
        shx[i] = pb[3 * i + 0];
        shy[i] = pb[3 * i + 1];
        shz[i] = pb[3 * i + 2];
    }
    __syncthreads();

    // points packed in pairs: pair p holds indices tid + 2p*1024, tid + (2p+1)*1024
    unsigned long long rx2[PPT / 2], ry2[PPT / 2], rz2[PPT / 2];
    float md[PPT];
#pragma unroll
    for (int p = 0; p < PPT / 2; p++) {
        int i0 = tid + ((2 * p) << 10);
        int i1 = i0 + 1024;
        rx2[p] = f2pack(shx[i0], shx[i1]);
        ry2[p] = f2pack(shy[i0], shy[i1]);
        rz2[p] = f2pack(shz[i0], shz[i1]);
        md[2 * p] = FLT_MAX; md[2 * p + 1] = FLT_MAX;
    }

    int cur = 0;
    for (int s = 0;; s++) {
        float qx = shx[cur], qy = shy[cur], qz = shz[cur];
        if (tid == 0) {
            float* oc = out_cent + ((size_t)b * MS + s) * 3;
            oc[0] = qx; oc[1] = qy; oc[2] = qz;
        }
        if (s == MS - 1) break;

        // negation is exact; add(r, -q) rounds identically to sub(r, q)
        unsigned long long nqx = f2pack(-qx, -qx);
        unsigned long long nqy = f2pack(-qy, -qy);
        unsigned long long nqz = f2pack(-qz, -qz);

        float tmax = -1.0f;
#pragma unroll
        for (int p = 0; p < PPT / 2; p++) {
            unsigned long long dx = f2add(rx2[p], nqx);
            unsigned long long dy = f2add(ry2[p], nqy);
            unsigned long long dz = f2add(rz2[p], nqz);
            unsigned long long sx = f2mul(dx, dx);
            unsigned long long sy = f2mul(dy, dy);
            unsigned long long sz = f2mul(dz, dz);
            unsigned long long d2 = f2add(f2add(sx, sy), sz);  // ((x²+y²)+z²)
            float a, c;
            f2unpack(a, c, d2);
            float m0 = fminf(md[2 * p],     a);
            float m1 = fminf(md[2 * p + 1], c);
            md[2 * p] = m0; md[2 * p + 1] = m1;
            tmax = fmaxf(tmax, fmaxf(m0, m1));
        }

        // block max (value only — fmax is exactly order-independent)
        float wmax = tmax;
#pragma unroll
        for (int o = 16; o; o >>= 1)
            wmax = fmaxf(wmax, __shfl_xor_sync(0xFFFFFFFFu, wmax, o));
        if (lane == 0) shredf[w] = wmax;
        __syncthreads();
        if (w == 0) {
            if (lane == 0) shidx = 0x7FFFFFFF;
            float g = shredf[lane];
#pragma unroll
            for (int o = 16; o; o >>= 1)
                g = fmaxf(g, __shfl_xor_sync(0xFFFFFFFFu, g, o));
            if (lane == 0) shmax = g;
        }
        __syncthreads();
        float g = shmax;
        if (tmax == g) {
            int k = 0;
#pragma unroll
            for (int kk = PPT - 1; kk >= 0; kk--)   // descending -> lowest k wins
                if (md[kk] == g) k = kk;
            atomicMin(&shidx, tid + (k << 10));     // lowest global idx = argmax first
        }
        __syncthreads();
        cur = shidx;
    }
}

// ---------------------------------------------------------------------------
// Kernel 2: 16-NN + gather. One WARP per centroid, 8 warps/CTA, 2048 CTAs.
// Top-16 list distributed across lanes 0..15, sorted ascending by (d2, idx)
// lexicographic key. Fast path: 32 distances + one ballot against the 16th-
// best threshold (usually zero). Inserts (~116/warp total) are warp-parallel:
// position via popc of key-compare ballot, shift via shfl_up.
// Candidates enter in ascending global index, re-checked against the updated
// threshold -> exactly lax.top_k ranking incl. stable ties (a rejected
// equal-key candidate is beaten by 16 keys that only ever improve).
// d2 pipeline matches the reference bitwise (verified round 3):
//   csum/psum: rn mul/add chain; dot: fma(cz,pz, fma(cy,py, cx*px));
//   d2 = ((csum - 2*dot) + psum).
// ---------------------------------------------------------------------------
__global__ __launch_bounds__(256)
void knn_kernel(const float* __restrict__ pos, const float* __restrict__ cent,
                float* __restrict__ out_grp) {
    __shared__ float4 shp[CH];
    const int lane = threadIdx.x & 31;
    const int wid  = threadIdx.x >> 5;
    const int b    = blockIdx.x >> 7;                    // 128 CTAs per batch
    const int m    = ((blockIdx.x & 127) * KW) + wid;    // centroid in batch

    const float* cp = cent + ((size_t)b * MS + m) * 3;
    const float cx = cp[0], cy = cp[1], cz = cp[2];
    const float csum = __fadd_rn(__fadd_rn(__fmul_rn(cx, cx), __fmul_rn(cy, cy)),
                                 __fmul_rn(cz, cz));
    const float* pb = pos + (size_t)b * NB * 3;

    float bd = FLT_MAX;          // lane's list entry (lanes 0..15 meaningful)
    int   bi = 0x7FFFFFFF;
    float th = FLT_MAX;          // current 16th-best distance

    for (int c0 = 0; c0 < NB; c0 += CH) {
        __syncthreads();
        for (int j = threadIdx.x; j < CH; j += 256) {
            float px = pb[3 * (c0 + j) + 0];
            float py = pb[3 * (c0 + j) + 1];
            float pz = pb[3 * (c0 + j) + 2];
            float ps = __fadd_rn(__fadd_rn(__fmul_rn(px, px), __fmul_rn(py, py)),
                                 __fmul_rn(pz, pz));
            shp[j] = make_float4(px, py, pz, ps);
        }
        __syncthreads();

        for (int jj = 0; jj < CH; jj += 32) {
            float4 p = shp[jj + lane];
            float dot = __fmaf_rn(cz, p.z,
                        __fmaf_rn(cy, p.y,
                        __fmul_rn(cx, p.x)));
            float d2 = __fadd_rn(__fsub_rn(csum, __fmul_rn(2.0f, dot)), p.w);

            unsigned mask = __ballot_sync(0xFFFFFFFFu, d2 < th);
            while (mask) {                       // ascending lane = ascending idx
                int src = __ffs(mask) - 1;
                mask &= mask - 1;
                float cd = __shfl_sync(0xFFFFFFFFu, d2, src);
                int   ci = c0 + jj + src;
                if (cd < th) {                   // recheck vs updated threshold
                    bool less = (bd < cd) || (bd == cd && bi < ci);
                    unsigned lm = __ballot_sync(0xFFFFFFFFu, less) & 0xFFFFu;
                    int pp = __popc(lm);         // sorted list -> prefix count
                    float ud = __shfl_up_sync(0xFFFFFFFFu, bd, 1);
                    int   ui = __shfl_up_sync(0xFFFFFFFFu, bi, 1);
                    if (lane == pp)      { bd = cd; bi = ci; }
                    else if (lane > pp)  { bd = ud; bi = ui; }
                    th = __shfl_sync(0xFFFFFFFFu, bd, 15);
                }
            }
        }
    }

    if (lane < KNN) {
        int i = bi;
        float* og = out_grp + ((size_t)((size_t)b * MS + m) * KNN + lane) * 3;
        og[0] = pb[3 * i + 0];
        og[1] = pb[3 * i + 1];
        og[2] = pb[3 * i + 2];
    }
}

// ---------------------------------------------------------------------------
// kernel_launch: d_in = [x (unused), pos, batch]; out = [centroids | groups].
// Graph-capturable: two kernel launches, no allocs, no syncs.
// ---------------------------------------------------------------------------
extern "C" void kernel_launch(void* const* d_in, const int* in_sizes, int n_in,
                              void* d_out, int out_size) {
    (void)in_sizes; (void)n_in; (void)out_size;
    const float* pos = (const float*)d_in[1];
    float* out      = (float*)d_out;
    float* out_cent = out;                              // B*M*3   = 49152
    float* out_grp  = out + (size_t)NBAT * MS * 3;      // B*M*K*3 = 786432

    const size_t fps_smem = (size_t)3 * NB * sizeof(float);
    cudaFuncSetAttribute(fps_kernel, cudaFuncAttributeMaxDynamicSharedMemorySize,
                         (int)fps_smem);

    fps_kernel<<<NBAT, 1024, fps_smem>>>(pos, out_cent);
    knn_kernel<<<NBAT * (MS / KW), 256>>>(pos, out_cent, out_grp);
}

// round 7
// speedup vs baseline: 2.3584x; 1.3218x over previous
#include <cuda_runtime.h>
#include <float.h>

#define NB   8192
#define NBAT 16
#define MS   1024
#define KNN  16
#define PPT  8        // FPS points per thread (8192 / 1024)
#define NPR  (PPT/2)  // packed pairs per thread
#define CH   2048     // KNN shared-memory chunk (points)
#define KW   8        // KNN warps per CTA (centroids per CTA)
#define FULLM 0xFFFFFFFFu

// ---- f32x2 helpers: two independent rn fp32 ops per instruction -----------
__device__ __forceinline__ unsigned long long f2pack(float lo, float hi) {
    unsigned long long d;
    asm("mov.b64 %0, {%1, %2};" : "=l"(d)
        : "r"(__float_as_uint(lo)), "r"(__float_as_uint(hi)));
    return d;
}
__device__ __forceinline__ void f2unpack(float& lo, float& hi, unsigned long long s) {
    unsigned a, b;
    asm("mov.b64 {%0, %1}, %2;" : "=r"(a), "=r"(b) : "l"(s));
    lo = __uint_as_float(a); hi = __uint_as_float(b);
}
__device__ __forceinline__ unsigned long long f2add(unsigned long long a,
                                                    unsigned long long b) {
    unsigned long long d;
    asm("add.rn.f32x2 %0, %1, %2;" : "=l"(d) : "l"(a), "l"(b));
    return d;
}
__device__ __forceinline__ unsigned long long f2mul(unsigned long long a,
                                                    unsigned long long b) {
    unsigned long long d;
    asm("mul.rn.f32x2 %0, %1, %2;" : "=l"(d) : "l"(a), "l"(b));
    return d;
}
__device__ __forceinline__ unsigned long long f2fma(unsigned long long a,
                                                    unsigned long long b,
                                                    unsigned long long c) {
    unsigned long long d;
    asm("fma.rn.f32x2 %0, %1, %2, %3;" : "=l"(d) : "l"(a), "l"(b), "l"(c));
    return d;
}

// ---------------------------------------------------------------------------
// Kernel 1: farthest point sampling. One CTA per batch, 1024 threads.
// Distance pass: packed f32x2 mul/add in the verified association
// ((dx*dx + dy*dy) + dz*dz) — bitwise identical per lane (no FMA; subtract =
// add of exactly-negated q). Per step:
//   redux.sync warp max -> 32 smem slots -> bar -> every warp re-reduces the
//   32 slots with redux.sync (no serial warp-0 phase) -> threads holding the
//   max recover lowest local index, atomicMin global index -> bar.
// 2 barriers/step, double-buffered index slot reset between them.
// Value/index semantics == jnp.argmax first occurrence, exact.
// ---------------------------------------------------------------------------
__global__ __launch_bounds__(1024, 1)
void fps_kernel(const float* __restrict__ pos, float* __restrict__ out_cent) {
    extern __shared__ float sh[];
    float* shx = sh;
    float* shy = sh + NB;
    float* shz = sh + 2 * NB;
    __shared__ unsigned shw[32];
    __shared__ int shidx2[2];

    const int b    = blockIdx.x;
    const int tid  = threadIdx.x;
    const int lane = tid & 31;
    const int w    = tid >> 5;
    const float* pb = pos + (size_t)b * NB * 3;

    for (int i = tid; i < NB; i += 1024) {
        shx[i] = pb[3 * i + 0];
        shy[i] = pb[3 * i + 1];
        shz[i] = pb[3 * i + 2];
    }
    if (tid == 0) { shidx2[0] = 0x7FFFFFFF; shidx2[1] = 0x7FFFFFFF; }
    __syncthreads();

    // pair p holds global indices tid + 2p*1024 (lo) and tid + (2p+1)*1024 (hi)
    unsigned long long rx2[NPR], ry2[NPR], rz2[NPR];
    float md[PPT];
#pragma unroll
    for (int p = 0; p < NPR; p++) {
        int i0 = tid + ((2 * p) << 10);
        int i1 = i0 + 1024;
        rx2[p] = f2pack(shx[i0], shx[i1]);
        ry2[p] = f2pack(shy[i0], shy[i1]);
        rz2[p] = f2pack(shz[i0], shz[i1]);
        md[2 * p] = FLT_MAX; md[2 * p + 1] = FLT_MAX;
    }

    int cur = 0;
    for (int s = 0;; s++) {
        float qx = shx[cur], qy = shy[cur], qz = shz[cur];
        if (tid == 0) {
            float* oc = out_cent + ((size_t)b * MS + s) * 3;
            oc[0] = qx; oc[1] = qy; oc[2] = qz;
        }
        if (s == MS - 1) break;

        unsigned long long nqx = f2pack(-qx, -qx);
        unsigned long long nqy = f2pack(-qy, -qy);
        unsigned long long nqz = f2pack(-qz, -qz);

        float tmax = 0.0f;   // all md >= 0, so 0 is the identity
#pragma unroll
        for (int p = 0; p < NPR; p++) {
            unsigned long long dx = f2add(rx2[p], nqx);
            unsigned long long dy = f2add(ry2[p], nqy);
            unsigned long long dz = f2add(rz2[p], nqz);
            unsigned long long sx = f2mul(dx, dx);
            unsigned long long sy = f2mul(dy, dy);
            unsigned long long sz = f2mul(dz, dz);
            unsigned long long d2 = f2add(f2add(sx, sy), sz);  // ((x²+y²)+z²)
            float a, c;
            f2unpack(a, c, d2);
            float m0 = fminf(md[2 * p],     a);
            float m1 = fminf(md[2 * p + 1], c);
            md[2 * p] = m0; md[2 * p + 1] = m1;
            tmax = fmaxf(tmax, fmaxf(m0, m1));
        }

        // non-negative floats: bit pattern is order-preserving as u32
        const unsigned tb = __float_as_uint(tmax);
        const unsigned wv = __reduce_max_sync(FULLM, tb);
        if (lane == 0) shw[w] = wv;
        __syncthreads();                                   // barrier 1
        const unsigned g = __reduce_max_sync(FULLM, shw[lane]);
        if (tid == 0) shidx2[(s + 1) & 1] = 0x7FFFFFFF;    // reset next slot
        if (tb == g) {
            const float gf = __uint_as_float(g);
            int k = 0;
#pragma unroll
            for (int kk = PPT - 1; kk >= 0; kk--)  // descending -> lowest k wins
                if (md[kk] == gf) k = kk;
            atomicMin(&shidx2[s & 1], tid + (k << 10));
        }
        __syncthreads();                                   // barrier 2
        cur = shidx2[s & 1];
    }
}

// ---------------------------------------------------------------------------
// Kernel 2: 16-NN + gather. One WARP per centroid, 8 warps/CTA, 2048 CTAs.
// 2 points per lane via packed f32x2 (SoA smem, aligned ld 64-bit pairs).
// d2 pipeline bitwise-matches the reference:
//   csum/psum: rn mul/add chain; dot: fma(cz,pz, fma(cy,py, cx*px));
//   d2 = (csum + (-2*dot)) + psum   [(-2)*dot is an exact sign flip of 2*dot,
//   so the add rounds identically to the reference's subtract].
// Top-16 distributed in lanes 0..15, sorted by lexicographic (d2, idx).
// Candidate order is now arbitrary (packed pairs), so stability is enforced
// explicitly: prefilter d2 <= th_d, then lex gate vs entry 15's (th_d, th_i).
// Kept set == 16 lex-smallest keys == lax.top_k stable result, order-free.
// ---------------------------------------------------------------------------
__global__ __launch_bounds__(256)
void knn_kernel(const float* __restrict__ pos, const float* __restrict__ cent,
                float* __restrict__ out_grp) {
    __shared__ alignas(16) float sx[CH];
    __shared__ alignas(16) float sy[CH];
    __shared__ alignas(16) float sz[CH];
    __shared__ alignas(16) float sw[CH];
    const int lane = threadIdx.x & 31;
    const int wid  = threadIdx.x >> 5;
    const int b    = blockIdx.x >> 7;                    // 128 CTAs per batch
    const int m    = ((blockIdx.x & 127) * KW) + wid;    // centroid in batch

    const float* cp = cent + ((size_t)b * MS + m) * 3;
    const float cx = cp[0], cy = cp[1], cz = cp[2];
    const float csum = __fadd_rn(__fadd_rn(__fmul_rn(cx, cx), __fmul_rn(cy, cy)),
                                 __fmul_rn(cz, cz));
    const unsigned long long cx2 = f2pack(cx, cx);
    const unsigned long long cy2 = f2pack(cy, cy);
    const unsigned long long cz2 = f2pack(cz, cz);
    const unsigned long long cs2 = f2pack(csum, csum);
    const unsigned long long n2  = f2pack(-2.0f, -2.0f);
    const float* pb = pos + (size_t)b * NB * 3;

    float bd = FLT_MAX;          // lane's list entry (lanes 0..15 meaningful)
    int   bi = 0x7FFFFFFF;
    float th_d = FLT_MAX;        // entry 15 (d2, idx)
    int   th_i = 0x7FFFFFFF;

    // warp-parallel sorted insert of candidate (cd, ci); gate + list are
    // maintained under lexicographic (d2, idx) order. All branches are
    // warp-uniform (cd/ci/th broadcast), so the syncs inside are safe.
    auto insert_mask = [&](unsigned mask, float d2v, int base, int par) {
        while (mask) {
            const int src = __ffs(mask) - 1;
            mask &= mask - 1;
            const float cd = __shfl_sync(FULLM, d2v, src);
            const int   ci = base + 2 * src + par;
            if ((cd < th_d) || (cd == th_d && ci < th_i)) {
                const bool less = (bd < cd) || (bd == cd && bi < ci);
                const unsigned lm = __ballot_sync(FULLM, less) & 0xFFFFu;
                const int pp = __popc(lm);
                const float ud = __shfl_up_sync(FULLM, bd, 1);
                const int   ui = __shfl_up_sync(FULLM, bi, 1);
                if (lane == pp)      { bd = cd; bi = ci; }
                else if (lane > pp)  { bd = ud; bi = ui; }
                th_d = __shfl_sync(FULLM, bd, 15);
                th_i = __shfl_sync(FULLM, bi, 15);
            }
        }
    };

    for (int c0 = 0; c0 < NB; c0 += CH) {
        __syncthreads();
        for (int j = threadIdx.x; j < CH; j += 256) {
            float px = pb[3 * (c0 + j) + 0];
            float py = pb[3 * (c0 + j) + 1];
            float pz = pb[3 * (c0 + j) + 2];
            float ps = __fadd_rn(__fadd_rn(__fmul_rn(px, px), __fmul_rn(py, py)),
                                 __fmul_rn(pz, pz));
            sx[j] = px; sy[j] = py; sz[j] = pz; sw[j] = ps;
        }
        __syncthreads();

        for (int jj = 0; jj < CH; jj += 64) {
            const int o = jj + 2 * lane;           // even pair base (8B aligned)
            const unsigned long long px2 =
                *reinterpret_cast<const unsigned long long*>(sx + o);
            const unsigned long long py2 =
                *reinterpret_cast<const unsigned long long*>(sy + o);
            const unsigned long long pz2 =
                *reinterpret_cast<const unsigned long long*>(sz + o);
            const unsigned long long pw2 =
                *reinterpret_cast<const unsigned long long*>(sw + o);

            const unsigned long long dot2 =
                f2fma(cz2, pz2, f2fma(cy2, py2, f2mul(cx2, px2)));
            const unsigned long long d2p =
                f2add(f2add(cs2, f2mul(n2, dot2)), pw2);
            float d2a, d2b;
            f2unpack(d2a, d2b, d2p);               // points o, o+1

            const unsigned ma = __ballot_sync(FULLM, d2a <= th_d);
            const unsigned mb = __ballot_sync(FULLM, d2b <= th_d);
            if (ma | mb) {
                insert_mask(ma, d2a, c0 + jj, 0);
                insert_mask(mb, d2b, c0 + jj, 1);
            }
        }
    }

    if (lane < KNN) {
        const int i = bi;
        float* og = out_grp + ((size_t)((size_t)b * MS + m) * KNN + lane) * 3;
        og[0] = pb[3 * i + 0];
        og[1] = pb[3 * i + 1];
        og[2] = pb[3 * i + 2];
    }
}

// ---------------------------------------------------------------------------
// kernel_launch: d_in = [x (unused), pos, batch]; out = [centroids | groups].
// Graph-capturable: two kernel launches, no allocs, no syncs.
// ---------------------------------------------------------------------------
extern "C" void kernel_launch(void* const* d_in, const int* in_sizes, int n_in,
                              void* d_out, int out_size) {
    (void)in_sizes; (void)n_in; (void)out_size;
    const float* pos = (const float*)d_in[1];
    float* out      = (float*)d_out;
    float* out_cent = out;                              // B*M*3   = 49152
    float* out_grp  = out + (size_t)NBAT * MS * 3;      // B*M*K*3 = 786432

    const size_t fps_smem = (size_t)3 * NB * sizeof(float);
    cudaFuncSetAttribute(fps_kernel, cudaFuncAttributeMaxDynamicSharedMemorySize,
                         (int)fps_smem);

    fps_kernel<<<NBAT, 1024, fps_smem>>>(pos, out_cent);
    knn_kernel<<<NBAT * (MS / KW), 256>>>(pos, out_cent, out_grp);
}